// round 1
// baseline (speedup 1.0000x reference)
#include <cuda_runtime.h>
#include <cstdint>

// ---------------------------------------------------------------------------
// RelationNetwork fused pipeline, fp32 with packed f32x2 FMA (sm_103a).
//
// Shapes (compile-time): N=M=1024 rois, G=16 groups, D=64 dim/group,
// E=64 emb, F=1024 feat.
//
// K1: C = roi @ [q_w;k_w;out_w]^T  -> g_qkp[seg][g][row][d]  (+q_b/k_b)
// K2: aff[n][g][m] = 0.125 * Q_g[n]·K_g[m]
// K3: per-n fused: pf = relu(pos_w @ pos_emb[:, n, :] + pos_b);
//     w = log(max(pf,1e-6)) + aff; softmax over m -> g_soft[g][n][m]
// K4: out[n][g*64+o] = sum_m soft[g][n][m] * P[g][m][o] + out_b
// ---------------------------------------------------------------------------

__device__ float g_qkp [3u * 16u * 1024u * 64u];   // 12 MB  [seg][g][row][64]
__device__ float g_aff [1024u * 16u * 1024u];      // 64 MB  [n][g][m]
__device__ float g_soft[16u * 1024u * 1024u];      // 64 MB  [g][n][m]

// ---- packed f32x2 helpers --------------------------------------------------
__device__ __forceinline__ unsigned long long pack2(float a, float b) {
    unsigned long long r;
    asm("mov.b64 %0, {%1, %2};" : "=l"(r)
        : "r"(__float_as_uint(a)), "r"(__float_as_uint(b)));
    return r;
}
__device__ __forceinline__ void unpack2(unsigned long long v, float& a, float& b) {
    unsigned int lo, hi;
    asm("mov.b64 {%0, %1}, %2;" : "=r"(lo), "=r"(hi) : "l"(v));
    a = __uint_as_float(lo);
    b = __uint_as_float(hi);
}
__device__ __forceinline__ unsigned long long fma2(unsigned long long a,
                                                   unsigned long long b,
                                                   unsigned long long c) {
    unsigned long long d;
    asm("fma.rn.f32x2 %0, %1, %2, %3;" : "=l"(d) : "l"(a), "l"(b), "l"(c));
    return d;
}

// ---------------------------------------------------------------------------
// K1: 1024x3072x1024 NT GEMM (both operands K-contiguous).
// 128x128 tile, 256 threads, 8x8 per thread, cols paired for f32x2.
// ---------------------------------------------------------------------------
__global__ __launch_bounds__(256) void k1_qkp(
    const float* __restrict__ A,
    const float* __restrict__ qw, const float* __restrict__ kw,
    const float* __restrict__ ow,
    const float* __restrict__ qb, const float* __restrict__ kb)
{
    __shared__ float As[16][132];
    __shared__ float Bs[16][132];
    const int tid  = threadIdx.x;
    const int row0 = blockIdx.y << 7;
    const int col0 = blockIdx.x << 7;
    const int seg  = col0 >> 10;
    const float* B = (seg == 0) ? qw : ((seg == 1) ? kw : ow);
    const int jb0  = col0 & 1023;

    const int lr = tid >> 2;          // 0..63 (rows lr, lr+64)
    const int lk = (tid & 3) << 2;    // 0,4,8,12
    const int tx = tid & 15;
    const int ty = tid >> 4;

    unsigned long long acc[8][4];
#pragma unroll
    for (int i = 0; i < 8; i++)
#pragma unroll
        for (int j = 0; j < 4; j++) acc[i][j] = 0ULL;

    const float* Ar0 = A + (row0 + lr) * 1024 + lk;
    const float* Ar1 = Ar0 + 64 * 1024;
    const float* Br0 = B + (jb0 + lr) * 1024 + lk;
    const float* Br1 = Br0 + 64 * 1024;

#pragma unroll 1
    for (int kt = 0; kt < 1024; kt += 16) {
        float4 a0 = *(const float4*)(Ar0 + kt);
        float4 a1 = *(const float4*)(Ar1 + kt);
        float4 b0 = *(const float4*)(Br0 + kt);
        float4 b1 = *(const float4*)(Br1 + kt);
        __syncthreads();
        As[lk + 0][lr] = a0.x; As[lk + 1][lr] = a0.y;
        As[lk + 2][lr] = a0.z; As[lk + 3][lr] = a0.w;
        As[lk + 0][lr + 64] = a1.x; As[lk + 1][lr + 64] = a1.y;
        As[lk + 2][lr + 64] = a1.z; As[lk + 3][lr + 64] = a1.w;
        Bs[lk + 0][lr] = b0.x; Bs[lk + 1][lr] = b0.y;
        Bs[lk + 2][lr] = b0.z; Bs[lk + 3][lr] = b0.w;
        Bs[lk + 0][lr + 64] = b1.x; Bs[lk + 1][lr + 64] = b1.y;
        Bs[lk + 2][lr + 64] = b1.z; Bs[lk + 3][lr + 64] = b1.w;
        __syncthreads();
#pragma unroll
        for (int kk = 0; kk < 16; kk++) {
            const float4 av0 = *(const float4*)&As[kk][ty << 3];
            const float4 av1 = *(const float4*)&As[kk][(ty << 3) + 4];
            const ulonglong2 bv0 = *(const ulonglong2*)&Bs[kk][tx << 3];
            const ulonglong2 bv1 = *(const ulonglong2*)&Bs[kk][(tx << 3) + 4];
            const float af[8] = {av0.x, av0.y, av0.z, av0.w,
                                 av1.x, av1.y, av1.z, av1.w};
            const unsigned long long bp[4] = {bv0.x, bv0.y, bv1.x, bv1.y};
#pragma unroll
            for (int i = 0; i < 8; i++) {
                const unsigned long long ad = pack2(af[i], af[i]);
#pragma unroll
                for (int jp = 0; jp < 4; jp++)
                    acc[i][jp] = fma2(ad, bp[jp], acc[i][jp]);
            }
        }
    }

    const int jl = jb0 + (tx << 3);   // 0..1023 inside segment
    float bias[8];
    if (seg == 0) {
        float4 t0 = *(const float4*)&qb[jl];
        float4 t1 = *(const float4*)&qb[jl + 4];
        bias[0] = t0.x; bias[1] = t0.y; bias[2] = t0.z; bias[3] = t0.w;
        bias[4] = t1.x; bias[5] = t1.y; bias[6] = t1.z; bias[7] = t1.w;
    } else if (seg == 1) {
        float4 t0 = *(const float4*)&kb[jl];
        float4 t1 = *(const float4*)&kb[jl + 4];
        bias[0] = t0.x; bias[1] = t0.y; bias[2] = t0.z; bias[3] = t0.w;
        bias[4] = t1.x; bias[5] = t1.y; bias[6] = t1.z; bias[7] = t1.w;
    } else {
#pragma unroll
        for (int j = 0; j < 8; j++) bias[j] = 0.0f;
    }
    const int g  = jl >> 6;
    const int d0 = jl & 63;
    float* ob = g_qkp + seg * (16 * 1024 * 64) + g * (1024 * 64) + d0;
#pragma unroll
    for (int i = 0; i < 8; i++) {
        const int n = row0 + (ty << 3) + i;
        float v[8];
#pragma unroll
        for (int jp = 0; jp < 4; jp++) {
            float x, y;
            unpack2(acc[i][jp], x, y);
            v[2 * jp]     = x + bias[2 * jp];
            v[2 * jp + 1] = y + bias[2 * jp + 1];
        }
        float4* dst = (float4*)(ob + n * 64);
        dst[0] = make_float4(v[0], v[1], v[2], v[3]);
        dst[1] = make_float4(v[4], v[5], v[6], v[7]);
    }
}

// ---------------------------------------------------------------------------
// K2: batched (16x) 1024x1024x64 NT GEMM: aff[n][g][m] = 0.125 * Q_g K_g^T
// ---------------------------------------------------------------------------
__global__ __launch_bounds__(256) void k2_aff()
{
    __shared__ float As[16][132];
    __shared__ float Bs[16][132];
    const int tid = threadIdx.x;
    const int m0  = blockIdx.x << 7;
    const int n0  = blockIdx.y << 7;
    const int g   = blockIdx.z;
    const float* Q = g_qkp + g * (1024 * 64);
    const float* K = g_qkp + (16 + g) * (1024 * 64);

    const int lr = tid >> 2;
    const int lk = (tid & 3) << 2;
    const int tx = tid & 15;
    const int ty = tid >> 4;

    unsigned long long acc[8][4];
#pragma unroll
    for (int i = 0; i < 8; i++)
#pragma unroll
        for (int j = 0; j < 4; j++) acc[i][j] = 0ULL;

#pragma unroll 1
    for (int kt = 0; kt < 64; kt += 16) {
        float4 a0 = *(const float4*)&Q[(n0 + lr) * 64 + kt + lk];
        float4 a1 = *(const float4*)&Q[(n0 + lr + 64) * 64 + kt + lk];
        float4 b0 = *(const float4*)&K[(m0 + lr) * 64 + kt + lk];
        float4 b1 = *(const float4*)&K[(m0 + lr + 64) * 64 + kt + lk];
        __syncthreads();
        As[lk + 0][lr] = a0.x; As[lk + 1][lr] = a0.y;
        As[lk + 2][lr] = a0.z; As[lk + 3][lr] = a0.w;
        As[lk + 0][lr + 64] = a1.x; As[lk + 1][lr + 64] = a1.y;
        As[lk + 2][lr + 64] = a1.z; As[lk + 3][lr + 64] = a1.w;
        Bs[lk + 0][lr] = b0.x; Bs[lk + 1][lr] = b0.y;
        Bs[lk + 2][lr] = b0.z; Bs[lk + 3][lr] = b0.w;
        Bs[lk + 0][lr + 64] = b1.x; Bs[lk + 1][lr + 64] = b1.y;
        Bs[lk + 2][lr + 64] = b1.z; Bs[lk + 3][lr + 64] = b1.w;
        __syncthreads();
#pragma unroll
        for (int kk = 0; kk < 16; kk++) {
            const float4 av0 = *(const float4*)&As[kk][ty << 3];
            const float4 av1 = *(const float4*)&As[kk][(ty << 3) + 4];
            const ulonglong2 bv0 = *(const ulonglong2*)&Bs[kk][tx << 3];
            const ulonglong2 bv1 = *(const ulonglong2*)&Bs[kk][(tx << 3) + 4];
            const float af[8] = {av0.x, av0.y, av0.z, av0.w,
                                 av1.x, av1.y, av1.z, av1.w};
            const unsigned long long bp[4] = {bv0.x, bv0.y, bv1.x, bv1.y};
#pragma unroll
            for (int i = 0; i < 8; i++) {
                const unsigned long long ad = pack2(af[i], af[i]);
#pragma unroll
                for (int jp = 0; jp < 4; jp++)
                    acc[i][jp] = fma2(ad, bp[jp], acc[i][jp]);
            }
        }
    }

    const int mc = m0 + (tx << 3);
#pragma unroll
    for (int i = 0; i < 8; i++) {
        const int n = n0 + (ty << 3) + i;
        float v[8];
#pragma unroll
        for (int jp = 0; jp < 4; jp++) {
            float x, y;
            unpack2(acc[i][jp], x, y);
            v[2 * jp]     = x * 0.125f;
            v[2 * jp + 1] = y * 0.125f;
        }
        float4* dst = (float4*)(g_aff + (n * 16 + g) * 1024 + mc);
        dst[0] = make_float4(v[0], v[1], v[2], v[3]);
        dst[1] = make_float4(v[4], v[5], v[6], v[7]);
    }
}

// ---------------------------------------------------------------------------
// K3: fused position projection + relu + log + add-aff + softmax.
// One block per n (1024 blocks, 256 threads, 4 m per thread, all 16 g).
// ---------------------------------------------------------------------------
__global__ __launch_bounds__(256) void k3_softmax(
    const float* __restrict__ pe,    // [64][1024 n][1024 m]
    const float* __restrict__ pw,    // [16][64]
    const float* __restrict__ pb)    // [16]
{
    __shared__ unsigned long long swd[16 * 64];   // duplicated weight pairs
    __shared__ float sb[16];
    __shared__ float red[16][8];
    const int n = blockIdx.x;
    const int t = threadIdx.x;

    for (int idx = t; idx < 1024; idx += 256) {
        const float w = pw[idx];
        swd[idx] = pack2(w, w);
    }
    if (t < 16) sb[t] = pb[t];
    __syncthreads();

    const int m0 = t << 2;
    unsigned long long acc[16][2];
#pragma unroll
    for (int gg = 0; gg < 16; gg++) { acc[gg][0] = 0ULL; acc[gg][1] = 0ULL; }

    const float* base = pe + (size_t)n * 1024 + m0;
    ulonglong2 v = *(const ulonglong2*)base;
#pragma unroll 1
    for (int e = 0; e < 64; e++) {
        const int en = (e + 1) & 63;   // wrap: extra e=0 reload is an L2 hit
        const ulonglong2 vn =
            *(const ulonglong2*)(base + (size_t)en * (1024 * 1024));
#pragma unroll
        for (int gg = 0; gg < 16; gg++) {
            const unsigned long long w = swd[(gg << 6) + e];
            acc[gg][0] = fma2(w, v.x, acc[gg][0]);
            acc[gg][1] = fma2(w, v.y, acc[gg][1]);
        }
        v = vn;
    }

    float wv[16][4];
    float mx[16];
#pragma unroll
    for (int gg = 0; gg < 16; gg++) {
        float x0, x1, x2, x3;
        unpack2(acc[gg][0], x0, x1);
        unpack2(acc[gg][1], x2, x3);
        const float bgg = sb[gg];
        const float4 av =
            *(const float4*)(g_aff + ((size_t)n * 16 + gg) * 1024 + m0);
        wv[gg][0] = __logf(fmaxf(x0 + bgg, 1e-6f)) + av.x;
        wv[gg][1] = __logf(fmaxf(x1 + bgg, 1e-6f)) + av.y;
        wv[gg][2] = __logf(fmaxf(x2 + bgg, 1e-6f)) + av.z;
        wv[gg][3] = __logf(fmaxf(x3 + bgg, 1e-6f)) + av.w;
        mx[gg] = fmaxf(fmaxf(wv[gg][0], wv[gg][1]),
                       fmaxf(wv[gg][2], wv[gg][3]));
    }

    const int lane = t & 31, wid = t >> 5;
#pragma unroll
    for (int gg = 0; gg < 16; gg++) {
        float m = mx[gg];
#pragma unroll
        for (int off = 16; off > 0; off >>= 1)
            m = fmaxf(m, __shfl_xor_sync(0xffffffffu, m, off));
        mx[gg] = m;
    }
    if (lane == 0) {
#pragma unroll
        for (int gg = 0; gg < 16; gg++) red[gg][wid] = mx[gg];
    }
    __syncthreads();
#pragma unroll
    for (int gg = 0; gg < 16; gg++) {
        float m = red[gg][0];
#pragma unroll
        for (int w = 1; w < 8; w++) m = fmaxf(m, red[gg][w]);
        mx[gg] = m;
    }
    __syncthreads();

    float sm[16];
#pragma unroll
    for (int gg = 0; gg < 16; gg++) {
        float s = 0.0f;
#pragma unroll
        for (int j = 0; j < 4; j++) {
            wv[gg][j] = __expf(wv[gg][j] - mx[gg]);
            s += wv[gg][j];
        }
#pragma unroll
        for (int off = 16; off > 0; off >>= 1)
            s += __shfl_xor_sync(0xffffffffu, s, off);
        sm[gg] = s;
    }
    if (lane == 0) {
#pragma unroll
        for (int gg = 0; gg < 16; gg++) red[gg][wid] = sm[gg];
    }
    __syncthreads();
#pragma unroll
    for (int gg = 0; gg < 16; gg++) {
        float s = red[gg][0];
#pragma unroll
        for (int w = 1; w < 8; w++) s += red[gg][w];
        const float inv = __fdividef(1.0f, s);
        const float4 o = make_float4(wv[gg][0] * inv, wv[gg][1] * inv,
                                     wv[gg][2] * inv, wv[gg][3] * inv);
        *(float4*)(g_soft + ((size_t)gg * 1024 + n) * 1024 + m0) = o;
    }
}

// ---------------------------------------------------------------------------
// K4: batched (16x) 1024x64x1024 NN GEMM: out[n][g*64+o] = soft_g @ P_g + out_b
// 64x64 tile, 128 threads, 4n x 8o per thread.
// ---------------------------------------------------------------------------
__global__ __launch_bounds__(128) void k4_out(float* __restrict__ out,
                                              const float* __restrict__ obias)
{
    __shared__ float As[16][68];   // [kk][n]
    __shared__ float Bs[16][68];   // [kk][o]
    const int tid = threadIdx.x;
    const int n0  = blockIdx.x << 6;
    const int g   = blockIdx.y;
    const float* S = g_soft + (size_t)g * (1024 * 1024);
    const float* P = g_qkp + (32 + g) * (1024 * 64);

    const int tx = tid & 7;          // o groups of 8
    const int ty = tid >> 3;         // n groups of 4 (0..15)
    const int ar = tid >> 2;         // 0..31 (rows ar, ar+32)
    const int ak = (tid & 3) << 2;
    const int br = tid >> 3;         // 0..15
    const int bc = (tid & 7) << 3;

    unsigned long long acc[4][4];
#pragma unroll
    for (int i = 0; i < 4; i++)
#pragma unroll
        for (int j = 0; j < 4; j++) acc[i][j] = 0ULL;

#pragma unroll 1
    for (int kt = 0; kt < 1024; kt += 16) {
        float4 a0 = *(const float4*)&S[(n0 + ar) * 1024 + kt + ak];
        float4 a1 = *(const float4*)&S[(n0 + ar + 32) * 1024 + kt + ak];
        float4 b0 = *(const float4*)&P[(kt + br) * 64 + bc];
        float4 b1 = *(const float4*)&P[(kt + br) * 64 + bc + 4];
        __syncthreads();
        As[ak + 0][ar] = a0.x; As[ak + 1][ar] = a0.y;
        As[ak + 2][ar] = a0.z; As[ak + 3][ar] = a0.w;
        As[ak + 0][ar + 32] = a1.x; As[ak + 1][ar + 32] = a1.y;
        As[ak + 2][ar + 32] = a1.z; As[ak + 3][ar + 32] = a1.w;
        *(float4*)&Bs[br][bc]     = b0;
        *(float4*)&Bs[br][bc + 4] = b1;
        __syncthreads();
#pragma unroll
        for (int kk = 0; kk < 16; kk++) {
            const float4 av = *(const float4*)&As[kk][ty << 2];
            const ulonglong2 bv0 = *(const ulonglong2*)&Bs[kk][tx << 3];
            const ulonglong2 bv1 = *(const ulonglong2*)&Bs[kk][(tx << 3) + 4];
            const unsigned long long bp[4] = {bv0.x, bv0.y, bv1.x, bv1.y};
            const float af[4] = {av.x, av.y, av.z, av.w};
#pragma unroll
            for (int i = 0; i < 4; i++) {
                const unsigned long long ad = pack2(af[i], af[i]);
#pragma unroll
                for (int jp = 0; jp < 4; jp++)
                    acc[i][jp] = fma2(ad, bp[jp], acc[i][jp]);
            }
        }
    }

    const int o0 = tx << 3;
    float bias[8];
    {
        float4 t0 = *(const float4*)&obias[(g << 6) + o0];
        float4 t1 = *(const float4*)&obias[(g << 6) + o0 + 4];
        bias[0] = t0.x; bias[1] = t0.y; bias[2] = t0.z; bias[3] = t0.w;
        bias[4] = t1.x; bias[5] = t1.y; bias[6] = t1.z; bias[7] = t1.w;
    }
#pragma unroll
    for (int i = 0; i < 4; i++) {
        const int nn = n0 + (ty << 2) + i;
        float v[8];
#pragma unroll
        for (int jp = 0; jp < 4; jp++) {
            float x, y;
            unpack2(acc[i][jp], x, y);
            v[2 * jp]     = x + bias[2 * jp];
            v[2 * jp + 1] = y + bias[2 * jp + 1];
        }
        float4* dst = (float4*)(out + nn * 1024 + (g << 6) + o0);
        dst[0] = make_float4(v[0], v[1], v[2], v[3]);
        dst[1] = make_float4(v[4], v[5], v[6], v[7]);
    }
}

// ---------------------------------------------------------------------------
extern "C" void kernel_launch(void* const* d_in, const int* in_sizes, int n_in,
                              void* d_out, int out_size)
{
    const float* roi = (const float*)d_in[0];
    const float* pe  = (const float*)d_in[1];
    int ix = 2;
    if (ix < n_in && in_sizes[ix] == 1) ix++;   // skip nongt_dim scalar if present
    const float* pos_w = (const float*)d_in[ix++];
    const float* pos_b = (const float*)d_in[ix++];
    const float* q_w   = (const float*)d_in[ix++];
    const float* q_b   = (const float*)d_in[ix++];
    const float* k_w   = (const float*)d_in[ix++];
    const float* k_b   = (const float*)d_in[ix++];
    const float* out_w = (const float*)d_in[ix++];
    const float* out_b = (const float*)d_in[ix++];
    float* out = (float*)d_out;

    k1_qkp   <<<dim3(24, 8),     256>>>(roi, q_w, k_w, out_w, q_b, k_b);
    k2_aff   <<<dim3(8, 8, 16),  256>>>();
    k3_softmax<<<1024,           256>>>(pe, pos_w, pos_b);
    k4_out   <<<dim3(16, 16),    128>>>(out, out_b);
}